// round 2
// baseline (speedup 1.0000x reference)
#include <cuda_runtime.h>
#include <cstdint>

// ============================ problem constants ============================
#define NROWS 16384
#define MCOLS 4096
#define DDIM  128
#define BI    128            // rows per CTA
#define KT    32             // K tile (j per iteration)
#define NKT   (MCOLS / KT)   // 128 iterations
#define THREADS 256

// pitch: 32 floats + 16B pad = 144 bytes (9 x 16B units -> conflict-free ldmatrix)
#define PITCH 144

// smem byte offsets
#define A0_OFF 0
#define A1_OFF 18432
#define B0_OFF 36864
#define B1_OFF 55296
#define TS_OFF 73728
#define RS_OFF 90112
#define ES_OFF 106496
#define ZS_OFF 122880
#define INV_OFF 123904
#define SMEM_BYTES 124416

// ============================ device scratch ===============================
__device__ float g_c[NROWS];    // exp(s_i)
__device__ float g_dd[NROWS];   // exp(0.2 s_i)
__device__ float g_ng[NROWS];   // -s_i
__device__ float g_t[MCOLS];    // t_j
__device__ float g_r[MCOLS];    // exp(-0.8 t_j)
__device__ float g_et[MCOLS];   // exp(t_j)
__device__ float g_UT[(size_t)DDIM * MCOLS]; // U^T[d][j] = tf32(exp(t_j)*V[j][d])

// ============================ asm helpers ==================================
__device__ __forceinline__ uint32_t smem_to_u32(const void* p) {
    uint32_t a;
    asm("{ .reg .u64 t; cvta.to.shared.u64 t, %1; cvt.u32.u64 %0, t; }"
        : "=r"(a) : "l"(p));
    return a;
}

#define LDM4(r0, r1, r2, r3, addr) \
    asm volatile("ldmatrix.sync.aligned.m8n8.x4.shared.b16 {%0,%1,%2,%3}, [%4];" \
        : "=r"(r0), "=r"(r1), "=r"(r2), "=r"(r3) : "r"(addr))

#define MMA_TF32(d, a, b) \
    asm volatile("mma.sync.aligned.m16n8k8.row.col.f32.tf32.tf32.f32 " \
        "{%0,%1,%2,%3}, {%4,%5,%6,%7}, {%8,%9}, {%0,%1,%2,%3};" \
        : "+f"((d)[0]), "+f"((d)[1]), "+f"((d)[2]), "+f"((d)[3]) \
        : "r"((a)[0]), "r"((a)[1]), "r"((a)[2]), "r"((a)[3]), \
          "r"((b)[0]), "r"((b)[1]))

#define CP_ASYNC16(dst, src) \
    asm volatile("cp.async.ca.shared.global [%0], [%1], 16;" :: "r"(dst), "l"(src))
#define CP_COMMIT() asm volatile("cp.async.commit_group;" ::: "memory")
#define CP_WAIT0()  asm volatile("cp.async.wait_group 0;" ::: "memory")

// ============================ prep kernels =================================
__global__ void prep_self(const float* __restrict__ sf, const float* __restrict__ a) {
    int row = blockIdx.x * 8 + (threadIdx.x >> 5);
    int lane = threadIdx.x & 31;
    float4 f = *(const float4*)&sf[(size_t)row * DDIM + lane * 4];
    float4 w = *(const float4*)&a[lane * 4];
    float v = f.x * w.x + f.y * w.y + f.z * w.z + f.w * w.w;
    #pragma unroll
    for (int o = 16; o > 0; o >>= 1) v += __shfl_xor_sync(0xffffffffu, v, o);
    if (lane == 0) {
        g_c[row]  = expf(v);
        g_dd[row] = expf(0.2f * v);
        g_ng[row] = -v;
    }
}

__global__ void prep_neigh(const float* __restrict__ fn, const float* __restrict__ a) {
    int row = blockIdx.x * 8 + (threadIdx.x >> 5);
    int lane = threadIdx.x & 31;
    float4 f = *(const float4*)&fn[(size_t)row * DDIM + lane * 4];
    float4 w = *(const float4*)&a[DDIM + lane * 4];
    float v = f.x * w.x + f.y * w.y + f.z * w.z + f.w * w.w;
    #pragma unroll
    for (int o = 16; o > 0; o >>= 1) v += __shfl_xor_sync(0xffffffffu, v, o);
    if (lane == 0) {
        g_t[row]  = v;
        g_r[row]  = expf(-0.8f * v);
        g_et[row] = expf(v);
    }
}

__global__ void prep_ut(const float* __restrict__ fn) {
    int j = blockIdx.x * 256 + threadIdx.x;
    int d = blockIdx.y;
    float v = g_et[j] * fn[(size_t)j * DDIM + d];
    uint32_t o;
    asm("cvt.rna.tf32.f32 %0, %1;" : "=r"(o) : "f"(v));
    g_UT[(size_t)d * MCOLS + j] = __uint_as_float(o);
}

// ============================ main kernel ==================================
// A value: branch-separated exp product, masked, truncated to tf32 (RZ) so
// the scalar Z accumulation matches exactly what the MMA multiplies.
__device__ __forceinline__ float aval(int m, float t, float rr,
                                      float cc, float dd, float ng) {
    float v = (t > ng) ? cc : dd * rr;
    v = __uint_as_float(__float_as_uint(v) & 0xffffe000u);
    return m ? v : 0.0f;
}

__device__ __forceinline__ void build_A(char* sm, int aoff, int kt, const int4* mk,
                                        int r, int kh, float cc, float dd, float ng,
                                        float& zacc) {
    const float4* tsv = (const float4*)(sm + TS_OFF);
    const float4* rsv = (const float4*)(sm + RS_OFF);
    const float4* esv = (const float4*)(sm + ES_OFF);
    const int idx = kt * 8 + kh * 4;
    char* dst = sm + aoff + r * PITCH + kh * 64;
    #pragma unroll
    for (int i = 0; i < 4; i++) {
        float4 t4 = tsv[idx + i];
        float4 r4 = rsv[idx + i];
        float4 e4 = esv[idx + i];
        int4 m = mk[i];
        float4 av;
        av.x = aval(m.x, t4.x, r4.x, cc, dd, ng);
        av.y = aval(m.y, t4.y, r4.y, cc, dd, ng);
        av.z = aval(m.z, t4.z, r4.z, cc, dd, ng);
        av.w = aval(m.w, t4.w, r4.w, cc, dd, ng);
        zacc = fmaf(av.x, e4.x, zacc);
        zacc = fmaf(av.y, e4.y, zacc);
        zacc = fmaf(av.z, e4.z, zacc);
        zacc = fmaf(av.w, e4.w, zacc);
        *(float4*)(dst + i * 16) = av;
    }
}

__device__ __forceinline__ void stage_B(uint32_t smb, int boff, int kt, int tid) {
    const int d = tid >> 1, h = tid & 1;
    uint32_t dst = smb + boff + d * PITCH + h * 64;
    const float* src = g_UT + (size_t)d * MCOLS + kt * KT + h * 16;
    #pragma unroll
    for (int i = 0; i < 4; i++)
        CP_ASYNC16(dst + i * 16, src + i * 4);
}

__global__ void __launch_bounds__(THREADS, 1)
attn_main(const int* __restrict__ nm, float* __restrict__ out) {
    extern __shared__ char sm[];
    const uint32_t smb = smem_to_u32(sm);
    const int tid = threadIdx.x;
    const int lane = tid & 31, wid = tid >> 5;
    // 8 warps = (k2, m2, n2); warp tile: 64m x 64n x 16k per KT
    const int ki = wid & 1, mi = (wid >> 1) & 1, ni = (wid >> 2) & 1;
    const int blockRow = blockIdx.x * BI;

    // ---- load k-constants (t, r, e^t) into smem ----
    {
        float4* t4 = (float4*)(sm + TS_OFF);
        float4* r4 = (float4*)(sm + RS_OFF);
        float4* e4 = (float4*)(sm + ES_OFF);
        const float4* gt = (const float4*)g_t;
        const float4* gr = (const float4*)g_r;
        const float4* ge = (const float4*)g_et;
        #pragma unroll
        for (int i = 0; i < 4; i++) {
            t4[i * 256 + tid] = gt[i * 256 + tid];
            r4[i * 256 + tid] = gr[i * 256 + tid];
            e4[i * 256 + tid] = ge[i * 256 + tid];
        }
    }

    // ---- per-row constants for A-build (thread owns one row, one k-half) ----
    const int r = tid & 127, kh = tid >> 7;
    const int grow = blockRow + r;
    const float cc = g_c[grow], dd = g_dd[grow], ng = g_ng[grow];
    float zacc = 0.0f;
    const int4* mrow = (const int4*)(nm + (size_t)grow * MCOLS);

    // ---- prologue: stage kt=0 ----
    int4 mk[4];
    #pragma unroll
    for (int i = 0; i < 4; i++) mk[i] = __ldcs(mrow + kh * 4 + i);
    stage_B(smb, B0_OFF, 0, tid);
    CP_COMMIT();
    __syncthreads();                       // constants visible
    build_A(sm, A0_OFF, 0, mk, r, kh, cc, dd, ng, zacc);
    CP_WAIT0();
    __syncthreads();                       // buffer 0 ready

    float acc[4][8][4];
    #pragma unroll
    for (int f = 0; f < 4; f++)
        #pragma unroll
        for (int n8 = 0; n8 < 8; n8++)
            #pragma unroll
            for (int q = 0; q < 4; q++) acc[f][n8][q] = 0.0f;

    // ldmatrix lane offsets (within a buffer)
    uint32_t aoff[4], boff[4];
    #pragma unroll
    for (int f = 0; f < 4; f++)
        aoff[f] = (uint32_t)((mi * 64 + f * 16 + (lane & 15)) * PITCH + (lane >> 4) * 16);
    #pragma unroll
    for (int p = 0; p < 4; p++)
        boff[p] = (uint32_t)((ni * 64 + p * 16 + (lane & 7) + ((lane >> 4) << 3)) * PITCH
                             + ((lane >> 3) & 1) * 16);

    for (int kt = 0; kt < NKT; kt++) {
        const int cur = kt & 1;
        const bool more = (kt + 1 < NKT);
        if (more) {
            #pragma unroll
            for (int i = 0; i < 4; i++)
                mk[i] = __ldcs(mrow + (kt + 1) * 8 + kh * 4 + i);
            stage_B(smb, cur ? B0_OFF : B1_OFF, kt + 1, tid);
            CP_COMMIT();
        }

        const uint32_t Ab = smb + (cur ? A1_OFF : A0_OFF);
        const uint32_t Bb = smb + (cur ? B1_OFF : B0_OFF);
        #pragma unroll
        for (int kk = 0; kk < 2; kk++) {
            const int k8 = ki * 2 + kk;
            uint32_t af[4][4], bf[8][2];
            #pragma unroll
            for (int f = 0; f < 4; f++)
                LDM4(af[f][0], af[f][1], af[f][2], af[f][3], Ab + aoff[f] + k8 * 32);
            #pragma unroll
            for (int p = 0; p < 4; p++)
                LDM4(bf[2 * p][0], bf[2 * p][1], bf[2 * p + 1][0], bf[2 * p + 1][1],
                     Bb + boff[p] + k8 * 32);
            #pragma unroll
            for (int f = 0; f < 4; f++)
                #pragma unroll
                for (int n8 = 0; n8 < 8; n8++)
                    MMA_TF32(acc[f][n8], af[f], bf[n8]);
        }

        if (more) {
            build_A(sm, cur ? A0_OFF : A1_OFF, kt + 1, mk, r, kh, cc, dd, ng, zacc);
            CP_WAIT0();
        }
        __syncthreads();
    }

    // ---- epilogue ----
    float* zsm  = (float*)(sm + ZS_OFF);
    float* invz = (float*)(sm + INV_OFF);
    float* red  = (float*)(sm + A0_OFF);   // reuse A/B buffers: 4 x 16KB tiles
    const int tileo = (mi * 2 + ni) * 4096;

    zsm[tid] = zacc;
    if (ki == 1) {  // k-split partial -> smem
        #pragma unroll
        for (int f = 0; f < 4; f++) {
            const int row = f * 16 + (lane >> 2);
            #pragma unroll
            for (int n8 = 0; n8 < 8; n8++) {
                const int col = n8 * 8 + (lane & 3) * 2;
                *(float2*)&red[tileo + row * 64 + col] =
                    make_float2(acc[f][n8][0], acc[f][n8][1]);
                *(float2*)&red[tileo + (row + 8) * 64 + col] =
                    make_float2(acc[f][n8][2], acc[f][n8][3]);
            }
        }
    }
    __syncthreads();
    if (tid < 128) {
        float z = zsm[tid] + zsm[tid + 128];
        invz[tid] = (z > 0.0f) ? 1.0f / z : 0.0f;
    }
    __syncthreads();
    if (ki == 0) {  // combine halves, scale by 1/Z, store
        #pragma unroll
        for (int f = 0; f < 4; f++) {
            const int row0 = f * 16 + (lane >> 2);
            const float i0 = invz[mi * 64 + row0];
            const float i1 = invz[mi * 64 + row0 + 8];
            const size_t go0 = (size_t)(blockRow + mi * 64 + row0) * DDIM;
            const size_t go1 = go0 + (size_t)8 * DDIM;
            #pragma unroll
            for (int n8 = 0; n8 < 8; n8++) {
                const int col = n8 * 8 + (lane & 3) * 2;
                float2 p0 = *(const float2*)&red[tileo + row0 * 64 + col];
                float2 p1 = *(const float2*)&red[tileo + (row0 + 8) * 64 + col];
                float2 o0 = make_float2((acc[f][n8][0] + p0.x) * i0,
                                        (acc[f][n8][1] + p0.y) * i0);
                float2 o1 = make_float2((acc[f][n8][2] + p1.x) * i1,
                                        (acc[f][n8][3] + p1.y) * i1);
                *(float2*)&out[go0 + ni * 64 + col] = o0;
                *(float2*)&out[go1 + ni * 64 + col] = o1;
            }
        }
    }
}

// ============================ launch =======================================
extern "C" void kernel_launch(void* const* d_in, const int* in_sizes, int n_in,
                              void* d_out, int out_size) {
    const float* sf = (const float*)d_in[0];   // self_feats      [16384,128] f32
    const float* fn = (const float*)d_in[1];   // features_neighs [4096,128]  f32
    const int*   nm = (const int*)d_in[2];     // neigh_matrix    [16384,4096] i32
    const float* a  = (const float*)d_in[3];   // a [256] f32
    float* out = (float*)d_out;

    prep_self<<<NROWS / 8, 256>>>(sf, a);
    prep_neigh<<<MCOLS / 8, 256>>>(fn, a);
    prep_ut<<<dim3(MCOLS / 256, DDIM), 256>>>(fn);

    cudaFuncSetAttribute(attn_main, cudaFuncAttributeMaxDynamicSharedMemorySize, SMEM_BYTES);
    attn_main<<<NROWS / BI, THREADS, SMEM_BYTES>>>(nm, out);
}

// round 3
// speedup vs baseline: 1.3132x; 1.3132x over previous
#include <cuda_runtime.h>
#include <cstdint>

// ============================ problem constants ============================
#define NROWS 16384
#define MCOLS 4096
#define DDIM  128
#define BI    128            // rows per CTA
#define KT    32             // K tile (j per iteration)
#define NKT   (MCOLS / KT)   // 128 iterations
#define THREADS 512

// pitch: 32 floats + 16B pad = 144 bytes (9 x 16B units -> conflict-free ldmatrix)
#define PITCH 144

// smem byte offsets
#define A0_OFF 0
#define A1_OFF 18432
#define B0_OFF 36864
#define B1_OFF 55296
#define TS_OFF 73728
#define RS_OFF 90112
#define ES_OFF 106496
#define ZS_OFF 122880
#define INV_OFF 123392
#define SMEM_BYTES 123904

// ============================ device scratch ===============================
__device__ float g_c[NROWS];    // exp(s_i)
__device__ float g_dd[NROWS];   // exp(0.2 s_i)
__device__ float g_ng[NROWS];   // -s_i
__device__ float g_t[MCOLS];    // t_j
__device__ float g_r[MCOLS];    // exp(-0.8 t_j)
__device__ float g_et[MCOLS];   // exp(t_j)
__device__ float g_UT[(size_t)DDIM * MCOLS]; // U^T[d][j] = tf32(exp(t_j)*V[j][d])

// ============================ asm helpers ==================================
__device__ __forceinline__ uint32_t smem_to_u32(const void* p) {
    uint32_t a;
    asm("{ .reg .u64 t; cvta.to.shared.u64 t, %1; cvt.u32.u64 %0, t; }"
        : "=r"(a) : "l"(p));
    return a;
}

#define LDM4(r0, r1, r2, r3, addr) \
    asm volatile("ldmatrix.sync.aligned.m8n8.x4.shared.b16 {%0,%1,%2,%3}, [%4];" \
        : "=r"(r0), "=r"(r1), "=r"(r2), "=r"(r3) : "r"(addr))

#define MMA_TF32(d, a, b) \
    asm volatile("mma.sync.aligned.m16n8k8.row.col.f32.tf32.tf32.f32 " \
        "{%0,%1,%2,%3}, {%4,%5,%6,%7}, {%8,%9}, {%0,%1,%2,%3};" \
        : "+f"((d)[0]), "+f"((d)[1]), "+f"((d)[2]), "+f"((d)[3]) \
        : "r"((a)[0]), "r"((a)[1]), "r"((a)[2]), "r"((a)[3]), \
          "r"((b)[0]), "r"((b)[1]))

#define CP_ASYNC16(dst, src) \
    asm volatile("cp.async.ca.shared.global [%0], [%1], 16;" :: "r"(dst), "l"(src))
#define CP_COMMIT() asm volatile("cp.async.commit_group;" ::: "memory")
#define CP_WAIT0()  asm volatile("cp.async.wait_group 0;" ::: "memory")

// ============================ prep kernels =================================
__global__ void prep_self(const float* __restrict__ sf, const float* __restrict__ a) {
    int row = blockIdx.x * 8 + (threadIdx.x >> 5);
    int lane = threadIdx.x & 31;
    float4 f = *(const float4*)&sf[(size_t)row * DDIM + lane * 4];
    float4 w = *(const float4*)&a[lane * 4];
    float v = f.x * w.x + f.y * w.y + f.z * w.z + f.w * w.w;
    #pragma unroll
    for (int o = 16; o > 0; o >>= 1) v += __shfl_xor_sync(0xffffffffu, v, o);
    if (lane == 0) {
        g_c[row]  = expf(v);
        g_dd[row] = expf(0.2f * v);
        g_ng[row] = -v;
    }
}

__global__ void prep_neigh(const float* __restrict__ fn, const float* __restrict__ a) {
    int row = blockIdx.x * 8 + (threadIdx.x >> 5);
    int lane = threadIdx.x & 31;
    float4 f = *(const float4*)&fn[(size_t)row * DDIM + lane * 4];
    float4 w = *(const float4*)&a[DDIM + lane * 4];
    float v = f.x * w.x + f.y * w.y + f.z * w.z + f.w * w.w;
    #pragma unroll
    for (int o = 16; o > 0; o >>= 1) v += __shfl_xor_sync(0xffffffffu, v, o);
    if (lane == 0) {
        g_t[row]  = v;
        g_r[row]  = expf(-0.8f * v);
        g_et[row] = expf(v);
    }
}

__global__ void prep_ut(const float* __restrict__ fn) {
    int j = blockIdx.x * 256 + threadIdx.x;
    int d = blockIdx.y;
    float v = g_et[j] * fn[(size_t)j * DDIM + d];
    uint32_t o;
    asm("cvt.rna.tf32.f32 %0, %1;" : "=r"(o) : "f"(v));
    g_UT[(size_t)d * MCOLS + j] = __uint_as_float(o);
}

// ============================ main kernel ==================================
// A value: branch-separated exp product, masked, truncated to tf32 (RZ) so
// the scalar Z accumulation matches exactly what the MMA multiplies.
__device__ __forceinline__ float aval(int m, float t, float rr,
                                      float cc, float dd, float ng) {
    float v = (t > ng) ? cc : dd * rr;
    v = __uint_as_float(__float_as_uint(v) & 0xffffe000u);
    return m ? v : 0.0f;
}

// Row-mapped A build: thread owns 2 fixed rows x 4 j. Row constants stay in
// registers; only 48B of t/r/e broadcast reads per thread per tile.
__device__ __forceinline__ void build_A(char* sm, int aoff, int kt,
                                        int4 m0, int4 m1, int r0, int jl,
                                        const float* cc, const float* dd,
                                        const float* ng, float* zacc) {
    const int ci = kt * 8 + (jl >> 2);
    float4 t4 = ((const float4*)(sm + TS_OFF))[ci];
    float4 r4 = ((const float4*)(sm + RS_OFF))[ci];
    float4 e4 = ((const float4*)(sm + ES_OFF))[ci];
    char* dst = sm + aoff + r0 * PITCH + jl * 4;

    float4 a0, a1;
    a0.x = aval(m0.x, t4.x, r4.x, cc[0], dd[0], ng[0]);
    a0.y = aval(m0.y, t4.y, r4.y, cc[0], dd[0], ng[0]);
    a0.z = aval(m0.z, t4.z, r4.z, cc[0], dd[0], ng[0]);
    a0.w = aval(m0.w, t4.w, r4.w, cc[0], dd[0], ng[0]);
    a1.x = aval(m1.x, t4.x, r4.x, cc[1], dd[1], ng[1]);
    a1.y = aval(m1.y, t4.y, r4.y, cc[1], dd[1], ng[1]);
    a1.z = aval(m1.z, t4.z, r4.z, cc[1], dd[1], ng[1]);
    a1.w = aval(m1.w, t4.w, r4.w, cc[1], dd[1], ng[1]);

    zacc[0] = fmaf(a0.x, e4.x, zacc[0]);
    zacc[0] = fmaf(a0.y, e4.y, zacc[0]);
    zacc[0] = fmaf(a0.z, e4.z, zacc[0]);
    zacc[0] = fmaf(a0.w, e4.w, zacc[0]);
    zacc[1] = fmaf(a1.x, e4.x, zacc[1]);
    zacc[1] = fmaf(a1.y, e4.y, zacc[1]);
    zacc[1] = fmaf(a1.z, e4.z, zacc[1]);
    zacc[1] = fmaf(a1.w, e4.w, zacc[1]);

    *(float4*)dst           = a0;
    *(float4*)(dst + PITCH) = a1;
}

__device__ __forceinline__ void stage_B(uint32_t smb, int boff, int kt, int tid) {
    const int d = tid >> 2, j4 = (tid & 3) * 2;
    uint32_t dst = smb + boff + d * PITCH + j4 * 16;
    const float* src = g_UT + (size_t)d * MCOLS + kt * KT + j4 * 4;
    CP_ASYNC16(dst,      src);
    CP_ASYNC16(dst + 16, src + 4);
}

__global__ void __launch_bounds__(THREADS, 1)
attn_main(const int* __restrict__ nm, float* __restrict__ out) {
    extern __shared__ char sm[];
    const uint32_t smb = smem_to_u32(sm);
    const int tid = threadIdx.x;
    const int lane = tid & 31, wid = tid >> 5;
    // 16 warps = (k2, m2, n4); warp tile: 64m x 32n x 16k per KT
    const int ki = wid & 1, mi = (wid >> 1) & 1, ni = wid >> 2;
    const int blockRow = blockIdx.x * BI;

    // ---- load k-constants (t, r, e^t) into smem ----
    {
        float4* t4 = (float4*)(sm + TS_OFF);
        float4* r4 = (float4*)(sm + RS_OFF);
        float4* e4 = (float4*)(sm + ES_OFF);
        const float4* gt = (const float4*)g_t;
        const float4* gr = (const float4*)g_r;
        const float4* ge = (const float4*)g_et;
        #pragma unroll
        for (int i = 0; i < 2; i++) {
            t4[i * 512 + tid] = gt[i * 512 + tid];
            r4[i * 512 + tid] = gr[i * 512 + tid];
            e4[i * 512 + tid] = ge[i * 512 + tid];
        }
    }

    // ---- per-thread row ownership: 2 fixed rows, 4 j per iteration ----
    const int jl = (tid & 7) * 4;        // j within 32-tile
    const int r0 = (tid >> 3) * 2;       // CTA-local rows r0, r0+1
    const int g0 = blockRow + r0;
    float cc[2] = { g_c[g0],  g_c[g0 + 1] };
    float dd[2] = { g_dd[g0], g_dd[g0 + 1] };
    float ng[2] = { g_ng[g0], g_ng[g0 + 1] };
    float zacc[2] = { 0.0f, 0.0f };
    const int4* mrow0 = (const int4*)(nm + (size_t)g0 * MCOLS);
    const int4* mrow1 = (const int4*)(nm + (size_t)(g0 + 1) * MCOLS);
    const int jc = jl >> 2;              // int4 index within tile

    // ---- prologue: stage kt=0 ----
    int4 mk0 = __ldcs(mrow0 + jc);
    int4 mk1 = __ldcs(mrow1 + jc);
    stage_B(smb, B0_OFF, 0, tid);
    CP_COMMIT();
    __syncthreads();                     // constants visible
    build_A(sm, A0_OFF, 0, mk0, mk1, r0, jl, cc, dd, ng, zacc);
    CP_WAIT0();
    __syncthreads();                     // buffer 0 ready

    float acc[4][4][4];
    #pragma unroll
    for (int f = 0; f < 4; f++)
        #pragma unroll
        for (int n8 = 0; n8 < 4; n8++)
            #pragma unroll
            for (int q = 0; q < 4; q++) acc[f][n8][q] = 0.0f;

    // ldmatrix lane offsets (within a buffer)
    uint32_t aoff[4], boff[2];
    #pragma unroll
    for (int f = 0; f < 4; f++)
        aoff[f] = (uint32_t)((mi * 64 + f * 16 + (lane & 15)) * PITCH + (lane >> 4) * 16);
    #pragma unroll
    for (int p = 0; p < 2; p++)
        boff[p] = (uint32_t)((ni * 32 + p * 16 + (lane & 7) + ((lane >> 4) << 3)) * PITCH
                             + ((lane >> 3) & 1) * 16);

    for (int kt = 0; kt < NKT; kt++) {
        const int cur = kt & 1;
        const bool more = (kt + 1 < NKT);
        if (more) {
            mk0 = __ldcs(mrow0 + (kt + 1) * 8 + jc);
            mk1 = __ldcs(mrow1 + (kt + 1) * 8 + jc);
            stage_B(smb, cur ? B0_OFF : B1_OFF, kt + 1, tid);
            CP_COMMIT();
        }

        const uint32_t Ab = smb + (cur ? A1_OFF : A0_OFF);
        const uint32_t Bb = smb + (cur ? B1_OFF : B0_OFF);
        #pragma unroll
        for (int kk = 0; kk < 2; kk++) {
            const int k8 = ki * 2 + kk;
            uint32_t af[4][4], bf[4][2];
            #pragma unroll
            for (int f = 0; f < 4; f++)
                LDM4(af[f][0], af[f][1], af[f][2], af[f][3], Ab + aoff[f] + k8 * 32);
            #pragma unroll
            for (int p = 0; p < 2; p++)
                LDM4(bf[2 * p][0], bf[2 * p][1], bf[2 * p + 1][0], bf[2 * p + 1][1],
                     Bb + boff[p] + k8 * 32);
            #pragma unroll
            for (int f = 0; f < 4; f++)
                #pragma unroll
                for (int n8 = 0; n8 < 4; n8++)
                    MMA_TF32(acc[f][n8], af[f], bf[n8]);
        }

        if (more) {
            build_A(sm, cur ? A0_OFF : A1_OFF, kt + 1, mk0, mk1, r0, jl, cc, dd, ng, zacc);
            CP_WAIT0();
        }
        __syncthreads();
    }

    // ---- Z: reduce over the 8 lanes sharing a row pair, then invert ----
    float* zsm  = (float*)(sm + ZS_OFF);
    float* invz = (float*)(sm + INV_OFF);
    #pragma unroll
    for (int o = 1; o < 8; o <<= 1) {
        zacc[0] += __shfl_xor_sync(0xffffffffu, zacc[0], o);
        zacc[1] += __shfl_xor_sync(0xffffffffu, zacc[1], o);
    }
    if ((lane & 7) == 0) { zsm[r0] = zacc[0]; zsm[r0 + 1] = zacc[1]; }
    __syncthreads();
    if (tid < 128) {
        float z = zsm[tid];
        invz[tid] = (z > 0.0f) ? 1.0f / z : 0.0f;
    }
    // ---- k-split reduce: ki=1 partials -> smem ----
    float* red = (float*)(sm + A0_OFF);  // 8 tiles x 64x32 = 64KB, reuse A/B bufs
    const int tileo = (mi * 4 + ni) * 2048;
    if (ki == 1) {
        #pragma unroll
        for (int f = 0; f < 4; f++) {
            const int row = f * 16 + (lane >> 2);
            #pragma unroll
            for (int n8 = 0; n8 < 4; n8++) {
                const int col = n8 * 8 + (lane & 3) * 2;
                *(float2*)&red[tileo + row * 32 + col] =
                    make_float2(acc[f][n8][0], acc[f][n8][1]);
                *(float2*)&red[tileo + (row + 8) * 32 + col] =
                    make_float2(acc[f][n8][2], acc[f][n8][3]);
            }
        }
    }
    __syncthreads();
    if (ki == 0) {  // combine halves, scale by 1/Z, store
        #pragma unroll
        for (int f = 0; f < 4; f++) {
            const int row0 = f * 16 + (lane >> 2);
            const float i0 = invz[mi * 64 + row0];
            const float i1 = invz[mi * 64 + row0 + 8];
            const size_t go0 = (size_t)(blockRow + mi * 64 + row0) * DDIM;
            const size_t go1 = go0 + (size_t)8 * DDIM;
            #pragma unroll
            for (int n8 = 0; n8 < 4; n8++) {
                const int col = n8 * 8 + (lane & 3) * 2;
                float2 p0 = *(const float2*)&red[tileo + row0 * 32 + col];
                float2 p1 = *(const float2*)&red[tileo + (row0 + 8) * 32 + col];
                float2 o0 = make_float2((acc[f][n8][0] + p0.x) * i0,
                                        (acc[f][n8][1] + p0.y) * i0);
                float2 o1 = make_float2((acc[f][n8][2] + p1.x) * i1,
                                        (acc[f][n8][3] + p1.y) * i1);
                *(float2*)&out[go0 + ni * 32 + col] = o0;
                *(float2*)&out[go1 + ni * 32 + col] = o1;
            }
        }
    }
}

// ============================ launch =======================================
extern "C" void kernel_launch(void* const* d_in, const int* in_sizes, int n_in,
                              void* d_out, int out_size) {
    const float* sf = (const float*)d_in[0];   // self_feats      [16384,128] f32
    const float* fn = (const float*)d_in[1];   // features_neighs [4096,128]  f32
    const int*   nm = (const int*)d_in[2];     // neigh_matrix    [16384,4096] i32
    const float* a  = (const float*)d_in[3];   // a [256] f32
    float* out = (float*)d_out;

    prep_self<<<NROWS / 8, 256>>>(sf, a);
    prep_neigh<<<MCOLS / 8, 256>>>(fn, a);
    prep_ut<<<dim3(MCOLS / 256, DDIM), 256>>>(fn);

    cudaFuncSetAttribute(attn_main, cudaFuncAttributeMaxDynamicSharedMemorySize, SMEM_BYTES);
    attn_main<<<NROWS / BI, THREADS, SMEM_BYTES>>>(nm, out);
}